// round 7
// baseline (speedup 1.0000x reference)
#include <cuda_runtime.h>
#include <cstdint>
#include <math.h>

#define L_TOT   12544
#define C_IN    64
#define C_OUT   64
#define K_TOT   576
#define M_TILE  128
#define KC      32
#define NCHUNK  (K_TOT / KC)   // 18

// ---- smem byte offsets ----
#define OFF_TMEM  0
#define OFF_MBAR0 8
#define OFF_MBAR1 16
#define OFF_WSUM  64                 // 64 floats
#define OFF_OFFT  320                // 576 ints (offset | tap<<20)
#define OFF_A     4096               // A[s][p]: s*49152 + p*16384  (96KB)
#define A_SSTRIDE 49152
#define A_PSTRIDE 16384
#define OFF_B     (OFF_A + 2*A_SSTRIDE)   // B[s]: s*8192 (16KB)
#define B_SSTRIDE 8192
#define SMEM_TOTAL (OFF_B + 2*B_SSTRIDE)  // 118784 = 116KB

// idesc: dtype=F32(1<<4), atype=TF32(2<<7), btype=TF32(2<<10), N=64(8<<17), M=128(8<<24)
#define IDESC_TF32 0x8100910u

#if defined(__CUDA_ARCH_FEAT_SM103_ALL) || \
    (defined(__CUDA_ARCH_SPECIFIC__) && (__CUDA_ARCH_SPECIFIC__ == 1030)) || \
    (defined(__CUDA_ARCH_FAMILY_SPECIFIC__) && (__CUDA_ARCH_FAMILY_SPECIFIC__ == 1030))
#define HAS_TCGEN05 1
#else
#define HAS_TCGEN05 0
#endif

__device__ float g_wsum[C_OUT];

__global__ void rowsum_kernel(const float* __restrict__ w) {
    int o = threadIdx.x;
    if (o >= C_OUT) return;
    float s = 0.f;
    #pragma unroll 8
    for (int k = 0; k < K_TOT; ++k) s += w[o * K_TOT + k];
    g_wsum[o] = s;
}

__device__ __forceinline__ float sigm(float x) { return 1.f / (1.f + __expf(-x)); }

__device__ __forceinline__ float epilogue(float S, float c1, float c2, float c3) {
    const float Kf = (float)K_TOT;
    float f = (-0.000287f * S + 0.266f * c1 - 0.1097f * c2) * (1.f / 75.f);

    float g1 = (0.11f  / 75.f) * Kf + 0.001309f * S + 0.00619f  * c1 - 0.009f    * c2 + 0.001383f * c3;
    float g2 = (0.179f / 75.f) * Kf - 0.0025f   * S + 0.00303f  * c1 - 0.00484f  * c2 + 0.0175f   * c3;
    float g3 = (0.238f / 75.f) * Kf - 0.000954f * S + 0.00187f  * c1 + 0.001877f * c2 + 0.01502f  * c3;
    float g4 = (0.388f / 75.f) * Kf - 0.00734f  * S + 0.001117f * c1 + 0.00752f  * c2 + 0.009f    * c3;
    float g5 = (0.507f / 75.f) * Kf - 0.01017f  * S + 0.000426f * c1 + 0.00837f  * c2 + 0.00413f  * c3;

    float t1 = sigm(10.f * (0.15f - f));
    float t2 = sigm(10.f * (0.23f - f));
    float t3 = sigm(10.f * (0.32f - f));
    float t4 = sigm(10.f * (0.39f - f));

    return g5 + t1 * (g1 - g2) + t2 * (g2 - g3) + t3 * (g3 - g4) + t4 * (g4 - g5);
}

#if HAS_TCGEN05
// ---------------- PTX helpers (sm_103a only) ----------------
__device__ __forceinline__ uint32_t smem_u32(const void* p) {
    uint32_t a;
    asm("{ .reg .u64 t; cvta.to.shared.u64 t, %1; cvt.u32.u64 %0, t; }" : "=r"(a) : "l"(p));
    return a;
}
__device__ __forceinline__ uint32_t elect_one() {
    uint32_t p;
    asm volatile("{ .reg .pred p; elect.sync _|p, 0xFFFFFFFF; selp.b32 %0, 1, 0, p; }" : "=r"(p));
    return p;
}
__device__ __forceinline__ float tf32r(float x) {
    float y; asm("cvt.rna.tf32.f32 %0, %1;" : "=f"(y) : "f"(x)); return y;
}

#define MBARRIER_INIT(addr, cnt) \
    asm volatile("mbarrier.init.shared.b64 [%0], %1;" :: "r"((uint32_t)(addr)), "r"((uint32_t)(cnt)) : "memory")

#define MBARRIER_WAIT_PARITY(mb, par) do {                                          \
    uint32_t _mb = (uint32_t)(mb), _p = (uint32_t)(par), _d;                        \
    asm volatile("{ .reg .pred p; mbarrier.try_wait.parity.acquire.cta.shared::cta.b64 p, [%1], %2; selp.b32 %0,1,0,p; }" \
        : "=r"(_d) : "r"(_mb), "r"(_p) : "memory");                                 \
    if (!_d) {                                                                      \
        asm volatile("{ .reg .pred P1;\n\t"                                         \
            "WL_%=: mbarrier.try_wait.parity.acquire.cta.shared::cta.b64 P1, [%0], %1, 0x989680;\n\t" \
            "@P1 bra.uni WD_%=;\n\t bra.uni WL_%=;\n\t WD_%=: }"                    \
            :: "r"(_mb), "r"(_p) : "memory");                                       \
    }                                                                               \
} while (0)

#define TCGEN05_ALLOC(sm, n) \
    asm volatile("tcgen05.alloc.cta_group::1.sync.aligned.shared::cta.b32 [%0], %1;" \
        :: "r"((uint32_t)(sm)), "r"((uint32_t)(n)) : "memory")
#define TCGEN05_RELINQ() \
    asm volatile("tcgen05.relinquish_alloc_permit.cta_group::1.sync.aligned;")
#define TCGEN05_DEALLOC(t, n) \
    asm volatile("tcgen05.dealloc.cta_group::1.sync.aligned.b32 %0, %1;" :: "r"(t), "r"((uint32_t)(n)))
#define TCGEN05_COMMIT(mb) \
    asm volatile("tcgen05.commit.cta_group::1.mbarrier::arrive::one.shared::cluster.b64 [%0];" \
        :: "r"((uint32_t)(mb)) : "memory")
#define TCGEN05_WAIT_LD()  asm volatile("tcgen05.wait::ld.sync.aligned;" ::: "memory")
#define TCGEN05_FENCE_AFTER() asm volatile("tcgen05.fence::after_thread_sync;" ::: "memory")

#define TCGEN05_LD_X16(r, addr) \
    asm volatile("tcgen05.ld.sync.aligned.32x32b.x16.b32 " \
        "{%0,%1,%2,%3,%4,%5,%6,%7,%8,%9,%10,%11,%12,%13,%14,%15}, [%16];" \
        : "=r"((r)[0]),"=r"((r)[1]),"=r"((r)[2]),"=r"((r)[3]),   \
          "=r"((r)[4]),"=r"((r)[5]),"=r"((r)[6]),"=r"((r)[7]),   \
          "=r"((r)[8]),"=r"((r)[9]),"=r"((r)[10]),"=r"((r)[11]), \
          "=r"((r)[12]),"=r"((r)[13]),"=r"((r)[14]),"=r"((r)[15]) \
        : "r"(addr))

// SW128 K-major smem descriptor (layout=2, version=1, SBO=64, LBO=1)
__device__ __forceinline__ uint64_t make_desc_sw128(uint32_t addr) {
    return ((uint64_t)2 << 61) | ((uint64_t)1 << 46) | ((uint64_t)64 << 32) |
           ((uint64_t)1 << 16) | ((uint64_t)(addr >> 4) & 0x3FFF);
}

__device__ __forceinline__ void mma_tf32_ss(uint32_t d, uint64_t ad, uint64_t bd,
                                            uint32_t idesc, uint32_t en) {
    asm volatile(
        "{ .reg .pred p; setp.ne.u32 p, %4, 0;\n\t"
        "tcgen05.mma.cta_group::1.kind::tf32 [%0], %1, %2, %3, {%5,%5,%5,%5}, p; }\n"
        :: "r"(d), "l"(ad), "l"(bd), "r"(idesc), "r"(en), "r"(0u) : "memory");
}
#endif // HAS_TCGEN05

// ---------------- main kernel ----------------
__global__ __launch_bounds__(256, 1) void conv_tc_kernel(
    const float* __restrict__ img,
    const float* __restrict__ wts,
    float* __restrict__ out)
{
#if HAS_TCGEN05
    extern __shared__ char smem[];
    const uint32_t sb = smem_u32(smem);
    const int tid = threadIdx.x, wid = tid >> 5, lane = tid & 31;
    const int bx = blockIdx.x;
    const int b = bx / 98, mb = bx - b * 98;
    const int m_base = mb * M_TILE;

    // TMEM alloc + mbar init + tables
    if (wid == 0) { TCGEN05_ALLOC(sb + OFF_TMEM, 256); TCGEN05_RELINQ(); }
    if (tid == 0) { MBARRIER_INIT(sb + OFF_MBAR0, 1); MBARRIER_INIT(sb + OFF_MBAR1, 1); }
    if (tid < C_OUT) ((float*)(smem + OFF_WSUM))[tid] = g_wsum[tid];
    for (int k = tid; k < K_TOT; k += 256) {
        int c = k / 9, t = k - c * 9, dy = t / 3, dx = t - dy * 3;
        ((int*)(smem + OFF_OFFT))[k] = (c * L_TOT + dy * 112 + dx) | (t << 20);
    }
    __syncthreads();
    uint32_t tmem;
    asm volatile("ld.shared.b32 %0, [%1];" : "=r"(tmem) : "r"(sb + OFF_TMEM));

    // per-thread staging geometry (all loop-invariant, hoisted)
    const int m  = tid & 127;
    const int gm = m_base + m;
    const int y  = gm / 112, x = gm - y * 112;
    const float* imgpre = img + (size_t)b * C_IN * L_TOT + ((y - 1) * 112 + (x - 1));
    unsigned ymask = 0, xmask = 0;
    #pragma unroll
    for (int d = 0; d < 3; ++d) {
        if ((unsigned)(y - 1 + d) < 112u) ymask |= 1u << d;
        if ((unsigned)(x - 1 + d) < 112u) xmask |= 1u << d;
    }
    unsigned vmask = 0;
    #pragma unroll
    for (int t = 0; t < 9; ++t)
        if (((ymask >> (t / 3)) & 1u) && ((xmask >> (t % 3)) & 1u)) vmask |= 1u << t;
    const bool allvalid = (vmask == 0x1FFu);

    // hoisted swizzled store offsets (4 quads per thread)
    uint32_t swoff[4];
    #pragma unroll
    for (int i = 0; i < 4; ++i) {
        uint32_t bo = (uint32_t)(m * 128 + (i * 2 + (tid >> 7)) * 16);
        swoff[i] = bo ^ ((bo >> 3) & 0x70);
    }
    // hoisted B store (thread -> o,q fixed)
    const int bo_o0 = tid >> 3, bo_q = tid & 7;
    uint32_t bsw0, bsw1;
    { uint32_t v = (uint32_t)(bo_o0 * 128 + bo_q * 16); bsw0 = v ^ ((v >> 3) & 0x70); }
    { uint32_t v = (uint32_t)((bo_o0 + 32) * 128 + bo_q * 16); bsw1 = v ^ ((v >> 3) & 0x70); }

    int ph0 = 0, ph1 = 0;
    for (int ch = 0; ch < NCHUNK; ++ch) {
        const int s = ch & 1;
        const uint32_t mbar = sb + (s ? OFF_MBAR1 : OFF_MBAR0);
        // wait until MMAs of chunk ch-2 (same buffer) are done before overwriting
        if (ch >= 2) {
            if (s) { MBARRIER_WAIT_PARITY(mbar, ph1); ph1 ^= 1; }
            else   { MBARRIER_WAIT_PARITY(mbar, ph0); ph0 ^= 1; }
        }
        const int k0 = ch * KC;
        char* Abase = smem + OFF_A + s * A_SSTRIDE;
        char* Bbase = smem + OFF_B + s * B_SSTRIDE;

        // ---- stage B tile ----
        {
            float4 w4 = *(const float4*)(wts + bo_o0 * K_TOT + k0 + bo_q * 4);
            w4.x = tf32r(w4.x); w4.y = tf32r(w4.y); w4.z = tf32r(w4.z); w4.w = tf32r(w4.w);
            *(float4*)(Bbase + bsw0) = w4;
            float4 w5 = *(const float4*)(wts + (bo_o0 + 32) * K_TOT + k0 + bo_q * 4);
            w5.x = tf32r(w5.x); w5.y = tf32r(w5.y); w5.z = tf32r(w5.z); w5.w = tf32r(w5.w);
            *(float4*)(Bbase + bsw1) = w5;
        }
        // ---- stage A tiles (u, u^2, u^3) ----
        const int* offp = (const int*)(smem + OFF_OFFT) + k0 + (tid >> 7) * 8;
        #pragma unroll
        for (int i = 0; i < 4; ++i) {
            int4 pk = *(const int4*)(offp + i * 8 - (i >> 1) * 12 + ((i & 1) ? 4 : 0));
            // quads: kq = i*2 + (tid>>7); table index = k0 + kq*4 = k0 + (tid>>7)*8? No — recompute plainly:
            pk = *(const int4*)((const int*)(smem + OFF_OFFT) + k0 + (i * 2 + (tid >> 7)) * 4);
            int pv[4] = {pk.x, pk.y, pk.z, pk.w};
            float4 r1, r2, r3;
            float* p1 = &r1.x; float* p2 = &r2.x; float* p3 = &r3.x;
            if (allvalid) {
                #pragma unroll
                for (int j = 0; j < 4; ++j) {
                    float v = __ldg(imgpre + (pv[j] & 0xFFFFF));
                    float v2 = v * v;
                    p1[j] = tf32r(v); p2[j] = tf32r(v2); p3[j] = tf32r(v2 * v);
                }
            } else {
                #pragma unroll
                for (int j = 0; j < 4; ++j) {
                    int p = pv[j];
                    float v = 0.f;
                    if ((vmask >> (p >> 20)) & 1u)
                        v = __ldg(imgpre + (p & 0xFFFFF));
                    float v2 = v * v;
                    p1[j] = tf32r(v); p2[j] = tf32r(v2); p3[j] = tf32r(v2 * v);
                }
            }
            *(float4*)(Abase + 0 * A_PSTRIDE + swoff[i]) = r1;
            *(float4*)(Abase + 1 * A_PSTRIDE + swoff[i]) = r2;
            *(float4*)(Abase + 2 * A_PSTRIDE + swoff[i]) = r3;
        }
        asm volatile("fence.proxy.async.shared::cta;" ::: "memory");
        __syncthreads();

        // ---- issue MMAs (no wait; same-D MMAs serialize in HW) ----
        if (wid == 0 && elect_one()) {
            const uint32_t ab = sb + OFF_A + s * A_SSTRIDE;
            const uint64_t ad1 = make_desc_sw128(ab);
            const uint64_t ad2 = make_desc_sw128(ab + A_PSTRIDE);
            const uint64_t ad3 = make_desc_sw128(ab + 2 * A_PSTRIDE);
            const uint64_t bd  = make_desc_sw128(sb + OFF_B + s * B_SSTRIDE);
            #pragma unroll
            for (int st = 0; st < 4; ++st) {
                uint32_t en = (ch > 0 || st > 0) ? 1u : 0u;
                mma_tf32_ss(tmem + 0,   ad1 + st * 2, bd + st * 2, IDESC_TF32, en);
                mma_tf32_ss(tmem + 64,  ad2 + st * 2, bd + st * 2, IDESC_TF32, en);
                mma_tf32_ss(tmem + 128, ad3 + st * 2, bd + st * 2, IDESC_TF32, en);
            }
            TCGEN05_COMMIT(mbar);
        }
    }
    // drain both pipelines
    MBARRIER_WAIT_PARITY(sb + OFF_MBAR0, ph0);
    MBARRIER_WAIT_PARITY(sb + OFF_MBAR1, ph1);

    // ---- fused epilogue from TMEM ----
    TCGEN05_FENCE_AFTER();
    const int msub  = wid & 3;
    const int nhalf = (wid >> 2) * 32;
    const float* sw = (const float*)(smem + OFF_WSUM);
    const int mg = m_base + msub * 32 + lane;

    #pragma unroll
    for (int h = 0; h < 2; ++h) {
        const int n0 = nhalf + h * 16;
        uint32_t a1[16], a2[16], a3[16];
        TCGEN05_LD_X16(a1, tmem + 0   + n0);
        TCGEN05_LD_X16(a2, tmem + 64  + n0);
        TCGEN05_LD_X16(a3, tmem + 128 + n0);
        TCGEN05_WAIT_LD();
        #pragma unroll
        for (int ni = 0; ni < 16; ++ni) {
            const int o = n0 + ni;
            float res = epilogue(sw[o],
                                 __uint_as_float(a1[ni]),
                                 __uint_as_float(a2[ni]),
                                 __uint_as_float(a3[ni]));
            out[(size_t)(b * C_OUT + o) * L_TOT + mg] = res;
        }
    }

    __syncthreads();
    if (wid == 0) TCGEN05_DEALLOC(tmem, 256);
#else
    // ---------- fallback for non-sm_103a compilation passes (never runs on GB300) ----------
    const int tid = threadIdx.x;
    const int bx = blockIdx.x;
    const int b = bx / 98, mb = bx - b * 98;
    const int m_base = mb * M_TILE;
    const float* imgb = img + (size_t)b * C_IN * L_TOT;

    for (int idx = tid; idx < M_TILE * C_OUT; idx += 256) {
        int m = idx & 127, o = idx >> 7;
        int gm = m_base + m;
        int y = gm / 112, x = gm - y * 112;
        float c1 = 0.f, c2 = 0.f, c3 = 0.f;
        for (int k = 0; k < K_TOT; ++k) {
            int c = k / 9, r = k - c * 9, dy = r / 3, dx = r - dy * 3;
            int iy = y + dy - 1, ix = x + dx - 1;
            float v = 0.f;
            if ((unsigned)iy < 112u && (unsigned)ix < 112u)
                v = imgb[c * L_TOT + iy * 112 + ix];
            float w = wts[o * K_TOT + k];
            c1 += v * w; c2 += v * v * w; c3 += v * v * v * w;
        }
        out[(size_t)(b * C_OUT + o) * L_TOT + gm] = epilogue(g_wsum[o], c1, c2, c3);
    }
#endif
}

extern "C" void kernel_launch(void* const* d_in, const int* in_sizes, int n_in,
                              void* d_out, int out_size) {
    const float* img = (const float*)d_in[0];
    const float* wts = (const float*)d_in[1];
    float* out = (float*)d_out;

    int B = in_sizes[0] / (C_IN * L_TOT);   // 8

    cudaFuncSetAttribute(conv_tc_kernel, cudaFuncAttributeMaxDynamicSharedMemorySize, SMEM_TOTAL);
    rowsum_kernel<<<1, 64>>>(wts);
    conv_tc_kernel<<<B * 98, 256, SMEM_TOTAL>>>(img, wts, out);
}

// round 8
// speedup vs baseline: 2.2202x; 2.2202x over previous
#include <cuda_runtime.h>
#include <cstdint>
#include <math.h>

#define L_TOT   12544
#define C_IN    64
#define C_OUT   64
#define K_TOT   576
#define M_TILE  128
#define KC      32
#define NCHUNK  (K_TOT / KC)   // 18

// ---- smem byte offsets (single-buffer, 58KB -> 2 CTAs/SM) ----
#define OFF_TMEM 0
#define OFF_MBAR 8
#define OFF_WSUM 64            // 64 floats
#define OFF_OFFT 320           // 576 ints
#define OFF_A1   3072          // [128][32] tf32, 16KB
#define OFF_A2   (OFF_A1 + 16384)
#define OFF_A3   (OFF_A2 + 16384)
#define OFF_B    (OFF_A3 + 16384)   // [64][32] tf32, 8KB
#define SMEM_TOTAL (OFF_B + 8192)   // 59392

// idesc: dtype=F32(1<<4), atype=TF32(2<<7), btype=TF32(2<<10), N=64(8<<17), M=128(8<<24)
#define IDESC_TF32 0x8100910u

#if defined(__CUDA_ARCH_FEAT_SM103_ALL) || \
    (defined(__CUDA_ARCH_SPECIFIC__) && (__CUDA_ARCH_SPECIFIC__ == 1030)) || \
    (defined(__CUDA_ARCH_FAMILY_SPECIFIC__) && (__CUDA_ARCH_FAMILY_SPECIFIC__ == 1030))
#define HAS_TCGEN05 1
#else
#define HAS_TCGEN05 0
#endif

__device__ float g_wsum[C_OUT];

__global__ void rowsum_kernel(const float* __restrict__ w) {
    int o = threadIdx.x;
    if (o >= C_OUT) return;
    float s = 0.f;
    #pragma unroll 8
    for (int k = 0; k < K_TOT; ++k) s += w[o * K_TOT + k];
    g_wsum[o] = s;
}

__device__ __forceinline__ float sigm(float x) { return 1.f / (1.f + __expf(-x)); }

__device__ __forceinline__ float epilogue(float S, float c1, float c2, float c3) {
    const float Kf = (float)K_TOT;
    float f = (-0.000287f * S + 0.266f * c1 - 0.1097f * c2) * (1.f / 75.f);

    float g1 = (0.11f  / 75.f) * Kf + 0.001309f * S + 0.00619f  * c1 - 0.009f    * c2 + 0.001383f * c3;
    float g2 = (0.179f / 75.f) * Kf - 0.0025f   * S + 0.00303f  * c1 - 0.00484f  * c2 + 0.0175f   * c3;
    float g3 = (0.238f / 75.f) * Kf - 0.000954f * S + 0.00187f  * c1 + 0.001877f * c2 + 0.01502f  * c3;
    float g4 = (0.388f / 75.f) * Kf - 0.00734f  * S + 0.001117f * c1 + 0.00752f  * c2 + 0.009f    * c3;
    float g5 = (0.507f / 75.f) * Kf - 0.01017f  * S + 0.000426f * c1 + 0.00837f  * c2 + 0.00413f  * c3;

    float t1 = sigm(10.f * (0.15f - f));
    float t2 = sigm(10.f * (0.23f - f));
    float t3 = sigm(10.f * (0.32f - f));
    float t4 = sigm(10.f * (0.39f - f));

    return g5 + t1 * (g1 - g2) + t2 * (g2 - g3) + t3 * (g3 - g4) + t4 * (g4 - g5);
}

#if HAS_TCGEN05
// ---------------- PTX helpers (sm_103a only) ----------------
__device__ __forceinline__ uint32_t smem_u32(const void* p) {
    uint32_t a;
    asm("{ .reg .u64 t; cvta.to.shared.u64 t, %1; cvt.u32.u64 %0, t; }" : "=r"(a) : "l"(p));
    return a;
}
__device__ __forceinline__ uint32_t elect_one() {
    uint32_t p;
    asm volatile("{ .reg .pred p; elect.sync _|p, 0xFFFFFFFF; selp.b32 %0, 1, 0, p; }" : "=r"(p));
    return p;
}
__device__ __forceinline__ float tf32r(float x) {
    float y; asm("cvt.rna.tf32.f32 %0, %1;" : "=f"(y) : "f"(x)); return y;
}

#define MBARRIER_INIT(addr, cnt) \
    asm volatile("mbarrier.init.shared.b64 [%0], %1;" :: "r"((uint32_t)(addr)), "r"((uint32_t)(cnt)) : "memory")

#define MBARRIER_WAIT_PARITY(mb, par) do {                                          \
    uint32_t _mb = (uint32_t)(mb), _p = (uint32_t)(par), _d;                        \
    asm volatile("{ .reg .pred p; mbarrier.try_wait.parity.acquire.cta.shared::cta.b64 p, [%1], %2; selp.b32 %0,1,0,p; }" \
        : "=r"(_d) : "r"(_mb), "r"(_p) : "memory");                                 \
    if (!_d) {                                                                      \
        asm volatile("{ .reg .pred P1;\n\t"                                         \
            "WL_%=: mbarrier.try_wait.parity.acquire.cta.shared::cta.b64 P1, [%0], %1, 0x989680;\n\t" \
            "@P1 bra.uni WD_%=;\n\t bra.uni WL_%=;\n\t WD_%=: }"                    \
            :: "r"(_mb), "r"(_p) : "memory");                                       \
    }                                                                               \
} while (0)

#define TCGEN05_ALLOC(sm, n) \
    asm volatile("tcgen05.alloc.cta_group::1.sync.aligned.shared::cta.b32 [%0], %1;" \
        :: "r"((uint32_t)(sm)), "r"((uint32_t)(n)) : "memory")
#define TCGEN05_RELINQ() \
    asm volatile("tcgen05.relinquish_alloc_permit.cta_group::1.sync.aligned;")
#define TCGEN05_DEALLOC(t, n) \
    asm volatile("tcgen05.dealloc.cta_group::1.sync.aligned.b32 %0, %1;" :: "r"(t), "r"((uint32_t)(n)))
#define TCGEN05_COMMIT(mb) \
    asm volatile("tcgen05.commit.cta_group::1.mbarrier::arrive::one.shared::cluster.b64 [%0];" \
        :: "r"((uint32_t)(mb)) : "memory")
#define TCGEN05_WAIT_LD()  asm volatile("tcgen05.wait::ld.sync.aligned;" ::: "memory")
#define TCGEN05_FENCE_AFTER() asm volatile("tcgen05.fence::after_thread_sync;" ::: "memory")

#define TCGEN05_LD_X16(r, addr) \
    asm volatile("tcgen05.ld.sync.aligned.32x32b.x16.b32 " \
        "{%0,%1,%2,%3,%4,%5,%6,%7,%8,%9,%10,%11,%12,%13,%14,%15}, [%16];" \
        : "=r"((r)[0]),"=r"((r)[1]),"=r"((r)[2]),"=r"((r)[3]),   \
          "=r"((r)[4]),"=r"((r)[5]),"=r"((r)[6]),"=r"((r)[7]),   \
          "=r"((r)[8]),"=r"((r)[9]),"=r"((r)[10]),"=r"((r)[11]), \
          "=r"((r)[12]),"=r"((r)[13]),"=r"((r)[14]),"=r"((r)[15]) \
        : "r"(addr))

// SW128 K-major smem descriptor (layout=2, version=1, SBO=64, LBO=1)
__device__ __forceinline__ uint64_t make_desc_sw128(uint32_t addr) {
    return ((uint64_t)2 << 61) | ((uint64_t)1 << 46) | ((uint64_t)64 << 32) |
           ((uint64_t)1 << 16) | ((uint64_t)(addr >> 4) & 0x3FFF);
}

__device__ __forceinline__ void mma_tf32_ss(uint32_t d, uint64_t ad, uint64_t bd,
                                            uint32_t idesc, uint32_t en) {
    asm volatile(
        "{ .reg .pred p; setp.ne.u32 p, %4, 0;\n\t"
        "tcgen05.mma.cta_group::1.kind::tf32 [%0], %1, %2, %3, {%5,%5,%5,%5}, p; }\n"
        :: "r"(d), "l"(ad), "l"(bd), "r"(idesc), "r"(en), "r"(0u) : "memory");
}
#endif // HAS_TCGEN05

// ---------------- main kernel ----------------
__global__ __launch_bounds__(256, 2) void conv_tc_kernel(
    const float* __restrict__ img,
    const float* __restrict__ wts,
    float* __restrict__ out)
{
#if HAS_TCGEN05
    extern __shared__ char smem[];
    const uint32_t sb = smem_u32(smem);
    const int tid = threadIdx.x, wid = tid >> 5, lane = tid & 31;
    const int bx = blockIdx.x;
    const int b = bx / 98, mb = bx - b * 98;
    const int m_base = mb * M_TILE;

    // TMEM alloc + mbar init + tables
    if (wid == 0) { TCGEN05_ALLOC(sb + OFF_TMEM, 256); TCGEN05_RELINQ(); }
    if (tid == 0) MBARRIER_INIT(sb + OFF_MBAR, 1);
    if (tid < C_OUT) ((float*)(smem + OFF_WSUM))[tid] = g_wsum[tid];
    for (int k = tid; k < K_TOT; k += 256) {
        int c = k / 9, t = k - c * 9, dy = t / 3, dx = t - dy * 3;
        ((int*)(smem + OFF_OFFT))[k] = (c * L_TOT + dy * 112 + dx) | (t << 20);
    }
    __syncthreads();
    uint32_t tmem;
    asm volatile("ld.shared.b32 %0, [%1];" : "=r"(tmem) : "r"(sb + OFF_TMEM));

    // per-thread staging geometry (loop-invariant)
    const int m  = tid & 127;
    const int gm = m_base + m;
    const int y  = gm / 112, x = gm - y * 112;
    const float* imgpre = img + (size_t)b * C_IN * L_TOT + ((y - 1) * 112 + (x - 1));
    unsigned vmask = 0;
    #pragma unroll
    for (int t = 0; t < 9; ++t) {
        int dy = t / 3, dx = t - dy * 3;
        if ((unsigned)(y - 1 + dy) < 112u && (unsigned)(x - 1 + dx) < 112u)
            vmask |= 1u << t;
    }
    const bool allvalid = (vmask == 0x1FFu);

    // hoisted swizzled A store offsets (4 quads per thread) and B offsets
    uint32_t swoff[4];
    #pragma unroll
    for (int i = 0; i < 4; ++i) {
        uint32_t bo = (uint32_t)(m * 128 + (i * 2 + (tid >> 7)) * 16);
        swoff[i] = bo ^ ((bo >> 3) & 0x70);
    }
    const int bo_o0 = tid >> 3, bo_q = tid & 7;
    uint32_t bsw0, bsw1;
    { uint32_t v = (uint32_t)(bo_o0 * 128 + bo_q * 16); bsw0 = v ^ ((v >> 3) & 0x70); }
    { uint32_t v = (uint32_t)((bo_o0 + 32) * 128 + bo_q * 16); bsw1 = v ^ ((v >> 3) & 0x70); }

    const uint64_t ad1 = make_desc_sw128(sb + OFF_A1);
    const uint64_t ad2 = make_desc_sw128(sb + OFF_A2);
    const uint64_t ad3 = make_desc_sw128(sb + OFF_A3);
    const uint64_t bd  = make_desc_sw128(sb + OFF_B);
    const int* offt = (const int*)(smem + OFF_OFFT);

    // ---- register prefetch buffers ----
    float av[16];
    float4 bw0, bw1;

    // prefetch for a chunk: 16 A values + 2 B float4s into registers
    #define PREFETCH(K0) do {                                                   \
        float4 _b0 = *(const float4*)(wts + bo_o0 * K_TOT + (K0) + bo_q * 4);   \
        float4 _b1 = *(const float4*)(wts + (bo_o0 + 32) * K_TOT + (K0) + bo_q * 4); \
        bw0 = _b0; bw1 = _b1;                                                   \
        _Pragma("unroll")                                                       \
        for (int _i = 0; _i < 4; ++_i) {                                        \
            int4 pk = *(const int4*)(offt + (K0) + (_i * 2 + (tid >> 7)) * 4);  \
            int pv[4] = {pk.x, pk.y, pk.z, pk.w};                               \
            _Pragma("unroll")                                                   \
            for (int _j = 0; _j < 4; ++_j) {                                    \
                int p = pv[_j];                                                 \
                float v = 0.f;                                                  \
                if (allvalid || ((vmask >> (p >> 20)) & 1u))                    \
                    v = __ldg(imgpre + (p & 0xFFFFF));                          \
                av[_i * 4 + _j] = v;                                            \
            }                                                                   \
        }                                                                       \
    } while (0)

    PREFETCH(0);

    int ph = 0;
    for (int ch = 0; ch < NCHUNK; ++ch) {
        // wait until previous chunk's MMAs finished reading smem
        if (ch > 0) { MBARRIER_WAIT_PARITY(sb + OFF_MBAR, ph); ph ^= 1; }

        // ---- store registers -> smem (with tf32 rounding) ----
        {
            float4 w4;
            w4.x = tf32r(bw0.x); w4.y = tf32r(bw0.y); w4.z = tf32r(bw0.z); w4.w = tf32r(bw0.w);
            *(float4*)(smem + OFF_B + bsw0) = w4;
            w4.x = tf32r(bw1.x); w4.y = tf32r(bw1.y); w4.z = tf32r(bw1.z); w4.w = tf32r(bw1.w);
            *(float4*)(smem + OFF_B + bsw1) = w4;
        }
        #pragma unroll
        for (int i = 0; i < 4; ++i) {
            float4 r1, r2, r3;
            float* p1 = &r1.x; float* p2 = &r2.x; float* p3 = &r3.x;
            #pragma unroll
            for (int j = 0; j < 4; ++j) {
                float v = av[i * 4 + j];
                float v2 = v * v;
                p1[j] = tf32r(v); p2[j] = tf32r(v2); p3[j] = tf32r(v2 * v);
            }
            *(float4*)(smem + OFF_A1 + swoff[i]) = r1;
            *(float4*)(smem + OFF_A2 + swoff[i]) = r2;
            *(float4*)(smem + OFF_A3 + swoff[i]) = r3;
        }
        asm volatile("fence.proxy.async.shared::cta;" ::: "memory");
        __syncthreads();

        // ---- issue MMAs for this chunk ----
        if (wid == 0 && elect_one()) {
            #pragma unroll
            for (int st = 0; st < 4; ++st) {
                uint32_t en = (ch > 0 || st > 0) ? 1u : 0u;
                mma_tf32_ss(tmem + 0,   ad1 + st * 2, bd + st * 2, IDESC_TF32, en);
                mma_tf32_ss(tmem + 64,  ad2 + st * 2, bd + st * 2, IDESC_TF32, en);
                mma_tf32_ss(tmem + 128, ad3 + st * 2, bd + st * 2, IDESC_TF32, en);
            }
            TCGEN05_COMMIT(sb + OFF_MBAR);
        }

        // ---- prefetch next chunk (overlaps the MMAs just issued) ----
        if (ch + 1 < NCHUNK) PREFETCH((ch + 1) * KC);
    }
    // drain last chunk
    MBARRIER_WAIT_PARITY(sb + OFF_MBAR, ph);

    // ---- fused epilogue from TMEM ----
    TCGEN05_FENCE_AFTER();
    const int msub  = wid & 3;
    const int nhalf = (wid >> 2) * 32;
    const float* sw = (const float*)(smem + OFF_WSUM);
    const int mg = m_base + msub * 32 + lane;

    #pragma unroll
    for (int h = 0; h < 2; ++h) {
        const int n0 = nhalf + h * 16;
        uint32_t a1[16], a2[16], a3[16];
        TCGEN05_LD_X16(a1, tmem + 0   + n0);
        TCGEN05_LD_X16(a2, tmem + 64  + n0);
        TCGEN05_LD_X16(a3, tmem + 128 + n0);
        TCGEN05_WAIT_LD();
        #pragma unroll
        for (int ni = 0; ni < 16; ++ni) {
            const int o = n0 + ni;
            float res = epilogue(sw[o],
                                 __uint_as_float(a1[ni]),
                                 __uint_as_float(a2[ni]),
                                 __uint_as_float(a3[ni]));
            out[(size_t)(b * C_OUT + o) * L_TOT + mg] = res;
        }
    }

    __syncthreads();
    if (wid == 0) TCGEN05_DEALLOC(tmem, 256);
#else
    // ---------- fallback for non-sm_103a compilation passes (never runs on GB300) ----------
    const int tid = threadIdx.x;
    const int bx = blockIdx.x;
    const int b = bx / 98, mb = bx - b * 98;
    const int m_base = mb * M_TILE;
    const float* imgb = img + (size_t)b * C_IN * L_TOT;

    for (int idx = tid; idx < M_TILE * C_OUT; idx += 256) {
        int m = idx & 127, o = idx >> 7;
        int gm = m_base + m;
        int y = gm / 112, x = gm - y * 112;
        float c1 = 0.f, c2 = 0.f, c3 = 0.f;
        for (int k = 0; k < K_TOT; ++k) {
            int c = k / 9, r = k - c * 9, dy = r / 3, dx = r - dy * 3;
            int iy = y + dy - 1, ix = x + dx - 1;
            float v = 0.f;
            if ((unsigned)iy < 112u && (unsigned)ix < 112u)
                v = imgb[c * L_TOT + iy * 112 + ix];
            float w = wts[o * K_TOT + k];
            c1 += v * w; c2 += v * v * w; c3 += v * v * v * w;
        }
        out[(size_t)(b * C_OUT + o) * L_TOT + gm] = epilogue(g_wsum[o], c1, c2, c3);
    }
#endif
}

extern "C" void kernel_launch(void* const* d_in, const int* in_sizes, int n_in,
                              void* d_out, int out_size) {
    const float* img = (const float*)d_in[0];
    const float* wts = (const float*)d_in[1];
    float* out = (float*)d_out;

    int B = in_sizes[0] / (C_IN * L_TOT);   // 8

    cudaFuncSetAttribute(conv_tc_kernel, cudaFuncAttributeMaxDynamicSharedMemorySize, SMEM_TOTAL);
    rowsum_kernel<<<1, 64>>>(wts);
    conv_tc_kernel<<<B * 98, 256, SMEM_TOTAL>>>(img, wts, out);
}

// round 9
// speedup vs baseline: 2.3363x; 1.0523x over previous
#include <cuda_runtime.h>
#include <cstdint>
#include <math.h>

#define L_TOT   12544
#define C_IN    64
#define C_OUT   64
#define K_TOT   576
#define M_TILE  128
#define KC      32
#define NCHUNK  (K_TOT / KC)   // 18
#define NTHREADS 512

// ---- smem byte offsets (single-buffer, ~58KB -> 2 CTAs/SM) ----
#define OFF_TMEM 0
#define OFF_MBAR 8
#define OFF_WSUM 64            // 64 floats
#define OFF_OFFT 320           // 576 ints
#define OFF_A1   3072          // [128][32] tf32, 16KB
#define OFF_A2   (OFF_A1 + 16384)
#define OFF_A3   (OFF_A2 + 16384)
#define OFF_B    (OFF_A3 + 16384)   // [64][32] tf32, 8KB
#define SMEM_TOTAL (OFF_B + 8192)   // 59392

// idesc: dtype=F32(1<<4), atype=TF32(2<<7), btype=TF32(2<<10), N=64(8<<17), M=128(8<<24)
#define IDESC_TF32 0x8100910u

#if defined(__CUDA_ARCH_FEAT_SM103_ALL) || \
    (defined(__CUDA_ARCH_SPECIFIC__) && (__CUDA_ARCH_SPECIFIC__ == 1030)) || \
    (defined(__CUDA_ARCH_FAMILY_SPECIFIC__) && (__CUDA_ARCH_FAMILY_SPECIFIC__ == 1030))
#define HAS_TCGEN05 1
#else
#define HAS_TCGEN05 0
#endif

__device__ float g_wsum[C_OUT];

__global__ void rowsum_kernel(const float* __restrict__ w) {
    int o = threadIdx.x;
    if (o >= C_OUT) return;
    float s = 0.f;
    #pragma unroll 8
    for (int k = 0; k < K_TOT; ++k) s += w[o * K_TOT + k];
    g_wsum[o] = s;
}

__device__ __forceinline__ float sigm(float x) { return 1.f / (1.f + __expf(-x)); }

__device__ __forceinline__ float epilogue(float S, float c1, float c2, float c3) {
    const float Kf = (float)K_TOT;
    float f = (-0.000287f * S + 0.266f * c1 - 0.1097f * c2) * (1.f / 75.f);

    float g1 = (0.11f  / 75.f) * Kf + 0.001309f * S + 0.00619f  * c1 - 0.009f    * c2 + 0.001383f * c3;
    float g2 = (0.179f / 75.f) * Kf - 0.0025f   * S + 0.00303f  * c1 - 0.00484f  * c2 + 0.0175f   * c3;
    float g3 = (0.238f / 75.f) * Kf - 0.000954f * S + 0.00187f  * c1 + 0.001877f * c2 + 0.01502f  * c3;
    float g4 = (0.388f / 75.f) * Kf - 0.00734f  * S + 0.001117f * c1 + 0.00752f  * c2 + 0.009f    * c3;
    float g5 = (0.507f / 75.f) * Kf - 0.01017f  * S + 0.000426f * c1 + 0.00837f  * c2 + 0.00413f  * c3;

    float t1 = sigm(10.f * (0.15f - f));
    float t2 = sigm(10.f * (0.23f - f));
    float t3 = sigm(10.f * (0.32f - f));
    float t4 = sigm(10.f * (0.39f - f));

    return g5 + t1 * (g1 - g2) + t2 * (g2 - g3) + t3 * (g3 - g4) + t4 * (g4 - g5);
}

#if HAS_TCGEN05
// ---------------- PTX helpers (sm_103a only) ----------------
__device__ __forceinline__ uint32_t smem_u32(const void* p) {
    uint32_t a;
    asm("{ .reg .u64 t; cvta.to.shared.u64 t, %1; cvt.u32.u64 %0, t; }" : "=r"(a) : "l"(p));
    return a;
}
__device__ __forceinline__ uint32_t elect_one() {
    uint32_t p;
    asm volatile("{ .reg .pred p; elect.sync _|p, 0xFFFFFFFF; selp.b32 %0, 1, 0, p; }" : "=r"(p));
    return p;
}
__device__ __forceinline__ float tf32r(float x) {
    float y; asm("cvt.rna.tf32.f32 %0, %1;" : "=f"(y) : "f"(x)); return y;
}

#define MBARRIER_INIT(addr, cnt) \
    asm volatile("mbarrier.init.shared.b64 [%0], %1;" :: "r"((uint32_t)(addr)), "r"((uint32_t)(cnt)) : "memory")

#define MBARRIER_WAIT_PARITY(mb, par) do {                                          \
    uint32_t _mb = (uint32_t)(mb), _p = (uint32_t)(par), _d;                        \
    asm volatile("{ .reg .pred p; mbarrier.try_wait.parity.acquire.cta.shared::cta.b64 p, [%1], %2; selp.b32 %0,1,0,p; }" \
        : "=r"(_d) : "r"(_mb), "r"(_p) : "memory");                                 \
    if (!_d) {                                                                      \
        asm volatile("{ .reg .pred P1;\n\t"                                         \
            "WL_%=: mbarrier.try_wait.parity.acquire.cta.shared::cta.b64 P1, [%0], %1, 0x989680;\n\t" \
            "@P1 bra.uni WD_%=;\n\t bra.uni WL_%=;\n\t WD_%=: }"                    \
            :: "r"(_mb), "r"(_p) : "memory");                                       \
    }                                                                               \
} while (0)

#define TCGEN05_ALLOC(sm, n) \
    asm volatile("tcgen05.alloc.cta_group::1.sync.aligned.shared::cta.b32 [%0], %1;" \
        :: "r"((uint32_t)(sm)), "r"((uint32_t)(n)) : "memory")
#define TCGEN05_RELINQ() \
    asm volatile("tcgen05.relinquish_alloc_permit.cta_group::1.sync.aligned;")
#define TCGEN05_DEALLOC(t, n) \
    asm volatile("tcgen05.dealloc.cta_group::1.sync.aligned.b32 %0, %1;" :: "r"(t), "r"((uint32_t)(n)))
#define TCGEN05_COMMIT(mb) \
    asm volatile("tcgen05.commit.cta_group::1.mbarrier::arrive::one.shared::cluster.b64 [%0];" \
        :: "r"((uint32_t)(mb)) : "memory")
#define TCGEN05_WAIT_LD()  asm volatile("tcgen05.wait::ld.sync.aligned;" ::: "memory")
#define TCGEN05_FENCE_AFTER() asm volatile("tcgen05.fence::after_thread_sync;" ::: "memory")

#define TCGEN05_LD_X16(r, addr) \
    asm volatile("tcgen05.ld.sync.aligned.32x32b.x16.b32 " \
        "{%0,%1,%2,%3,%4,%5,%6,%7,%8,%9,%10,%11,%12,%13,%14,%15}, [%16];" \
        : "=r"((r)[0]),"=r"((r)[1]),"=r"((r)[2]),"=r"((r)[3]),   \
          "=r"((r)[4]),"=r"((r)[5]),"=r"((r)[6]),"=r"((r)[7]),   \
          "=r"((r)[8]),"=r"((r)[9]),"=r"((r)[10]),"=r"((r)[11]), \
          "=r"((r)[12]),"=r"((r)[13]),"=r"((r)[14]),"=r"((r)[15]) \
        : "r"(addr))

// SW128 K-major smem descriptor (layout=2, version=1, SBO=64, LBO=1)
__device__ __forceinline__ uint64_t make_desc_sw128(uint32_t addr) {
    return ((uint64_t)2 << 61) | ((uint64_t)1 << 46) | ((uint64_t)64 << 32) |
           ((uint64_t)1 << 16) | ((uint64_t)(addr >> 4) & 0x3FFF);
}

__device__ __forceinline__ void mma_tf32_ss(uint32_t d, uint64_t ad, uint64_t bd,
                                            uint32_t idesc, uint32_t en) {
    asm volatile(
        "{ .reg .pred p; setp.ne.u32 p, %4, 0;\n\t"
        "tcgen05.mma.cta_group::1.kind::tf32 [%0], %1, %2, %3, {%5,%5,%5,%5}, p; }\n"
        :: "r"(d), "l"(ad), "l"(bd), "r"(idesc), "r"(en), "r"(0u) : "memory");
}
#endif // HAS_TCGEN05

// ---------------- main kernel ----------------
__global__ __launch_bounds__(NTHREADS, 2) void conv_tc_kernel(
    const float* __restrict__ img,
    const float* __restrict__ wts,
    float* __restrict__ out)
{
#if HAS_TCGEN05
    extern __shared__ char smem[];
    const uint32_t sb = smem_u32(smem);
    const int tid = threadIdx.x, wid = tid >> 5, lane = tid & 31;
    const int bx = blockIdx.x;
    const int b = bx / 98, mb = bx - b * 98;
    const int m_base = mb * M_TILE;

    // TMEM alloc + mbar init + tables
    if (wid == 0) { TCGEN05_ALLOC(sb + OFF_TMEM, 256); TCGEN05_RELINQ(); }
    if (tid == 0) MBARRIER_INIT(sb + OFF_MBAR, 1);
    if (tid < C_OUT) ((float*)(smem + OFF_WSUM))[tid] = g_wsum[tid];
    for (int k = tid; k < K_TOT; k += NTHREADS) {
        int c = k / 9, t = k - c * 9, dy = t / 3, dx = t - dy * 3;
        ((int*)(smem + OFF_OFFT))[k] = (c * L_TOT + dy * 112 + dx) | (t << 20);
    }
    __syncthreads();
    uint32_t tmem;
    asm volatile("ld.shared.b32 %0, [%1];" : "=r"(tmem) : "r"(sb + OFF_TMEM));

    // per-thread staging geometry (loop-invariant)
    const int m  = tid & 127;
    const int qg = tid >> 7;          // 0..3 quad-group; this thread stages quads qg*2, qg*2+1
    const int gm = m_base + m;
    const int y  = gm / 112, x = gm - y * 112;
    const float* imgpre = img + (size_t)b * C_IN * L_TOT + ((y - 1) * 112 + (x - 1));
    unsigned vmask = 0;
    #pragma unroll
    for (int t = 0; t < 9; ++t) {
        int dy = t / 3, dx = t - dy * 3;
        if ((unsigned)(y - 1 + dy) < 112u && (unsigned)(x - 1 + dx) < 112u)
            vmask |= 1u << t;
    }
    const bool allvalid = (vmask == 0x1FFu);

    // hoisted swizzled A store offsets (2 quads per thread) + B offset (1 task)
    uint32_t swoff[2];
    #pragma unroll
    for (int i = 0; i < 2; ++i) {
        uint32_t bo = (uint32_t)(m * 128 + (qg * 2 + i) * 16);
        swoff[i] = bo ^ ((bo >> 3) & 0x70);
    }
    const int bo_o = tid >> 3, bo_q = tid & 7;
    uint32_t bsw;
    { uint32_t v = (uint32_t)(bo_o * 128 + bo_q * 16); bsw = v ^ ((v >> 3) & 0x70); }

    const uint64_t ad1 = make_desc_sw128(sb + OFF_A1);
    const uint64_t ad2 = make_desc_sw128(sb + OFF_A2);
    const uint64_t ad3 = make_desc_sw128(sb + OFF_A3);
    const uint64_t bd  = make_desc_sw128(sb + OFF_B);
    const int* offt = (const int*)(smem + OFF_OFFT);

    // ---- register prefetch buffers (half of R8's: 8 A values + 1 B float4) ----
    float av[8];
    float4 bw;

    #define PREFETCH(K0) do {                                                   \
        bw = *(const float4*)(wts + bo_o * K_TOT + (K0) + bo_q * 4);            \
        _Pragma("unroll")                                                       \
        for (int _i = 0; _i < 2; ++_i) {                                        \
            int4 pk = *(const int4*)(offt + (K0) + (qg * 2 + _i) * 4);          \
            int pv[4] = {pk.x, pk.y, pk.z, pk.w};                               \
            _Pragma("unroll")                                                   \
            for (int _j = 0; _j < 4; ++_j) {                                    \
                int p = pv[_j];                                                 \
                float v = 0.f;                                                  \
                if (allvalid || ((vmask >> (p >> 20)) & 1u))                    \
                    v = __ldg(imgpre + (p & 0xFFFFF));                          \
                av[_i * 4 + _j] = v;                                            \
            }                                                                   \
        }                                                                       \
    } while (0)

    PREFETCH(0);

    int ph = 0;
    for (int ch = 0; ch < NCHUNK; ++ch) {
        // wait until previous chunk's MMAs finished reading smem
        if (ch > 0) { MBARRIER_WAIT_PARITY(sb + OFF_MBAR, ph); ph ^= 1; }

        // ---- store registers -> smem (with tf32 rounding) ----
        {
            float4 w4;
            w4.x = tf32r(bw.x); w4.y = tf32r(bw.y); w4.z = tf32r(bw.z); w4.w = tf32r(bw.w);
            *(float4*)(smem + OFF_B + bsw) = w4;
        }
        #pragma unroll
        for (int i = 0; i < 2; ++i) {
            float4 r1, r2, r3;
            float* p1 = &r1.x; float* p2 = &r2.x; float* p3 = &r3.x;
            #pragma unroll
            for (int j = 0; j < 4; ++j) {
                float v = av[i * 4 + j];
                float v2 = v * v;
                p1[j] = tf32r(v); p2[j] = tf32r(v2); p3[j] = tf32r(v2 * v);
            }
            *(float4*)(smem + OFF_A1 + swoff[i]) = r1;
            *(float4*)(smem + OFF_A2 + swoff[i]) = r2;
            *(float4*)(smem + OFF_A3 + swoff[i]) = r3;
        }
        asm volatile("fence.proxy.async.shared::cta;" ::: "memory");
        __syncthreads();

        // ---- issue MMAs for this chunk ----
        if (wid == 0 && elect_one()) {
            #pragma unroll
            for (int st = 0; st < 4; ++st) {
                uint32_t en = (ch > 0 || st > 0) ? 1u : 0u;
                mma_tf32_ss(tmem + 0,   ad1 + st * 2, bd + st * 2, IDESC_TF32, en);
                mma_tf32_ss(tmem + 64,  ad2 + st * 2, bd + st * 2, IDESC_TF32, en);
                mma_tf32_ss(tmem + 128, ad3 + st * 2, bd + st * 2, IDESC_TF32, en);
            }
            TCGEN05_COMMIT(sb + OFF_MBAR);
        }

        // ---- prefetch next chunk (overlaps the MMAs just issued) ----
        if (ch + 1 < NCHUNK) PREFETCH((ch + 1) * KC);
    }
    // drain last chunk
    MBARRIER_WAIT_PARITY(sb + OFF_MBAR, ph);

    // ---- fused epilogue from TMEM (16 warps: warp -> (m-subpartition, 16-col group)) ----
    TCGEN05_FENCE_AFTER();
    const int msub = wid & 3;
    const int n0   = (wid >> 2) * 16;
    const float* sw = (const float*)(smem + OFF_WSUM);
    const int mg = m_base + msub * 32 + lane;

    {
        uint32_t a1[16], a2[16], a3[16];
        TCGEN05_LD_X16(a1, tmem + 0   + n0);
        TCGEN05_LD_X16(a2, tmem + 64  + n0);
        TCGEN05_LD_X16(a3, tmem + 128 + n0);
        TCGEN05_WAIT_LD();
        #pragma unroll
        for (int ni = 0; ni < 16; ++ni) {
            const int o = n0 + ni;
            float res = epilogue(sw[o],
                                 __uint_as_float(a1[ni]),
                                 __uint_as_float(a2[ni]),
                                 __uint_as_float(a3[ni]));
            out[(size_t)(b * C_OUT + o) * L_TOT + mg] = res;
        }
    }

    __syncthreads();
    if (wid == 0) TCGEN05_DEALLOC(tmem, 256);
#else
    // ---------- fallback for non-sm_103a compilation passes (never runs on GB300) ----------
    const int tid = threadIdx.x;
    const int bx = blockIdx.x;
    const int b = bx / 98, mb = bx - b * 98;
    const int m_base = mb * M_TILE;
    const float* imgb = img + (size_t)b * C_IN * L_TOT;

    for (int idx = tid; idx < M_TILE * C_OUT; idx += NTHREADS) {
        int m = idx & 127, o = idx >> 7;
        int gm = m_base + m;
        int y = gm / 112, x = gm - y * 112;
        float c1 = 0.f, c2 = 0.f, c3 = 0.f;
        for (int k = 0; k < K_TOT; ++k) {
            int c = k / 9, r = k - c * 9, dy = r / 3, dx = r - dy * 3;
            int iy = y + dy - 1, ix = x + dx - 1;
            float v = 0.f;
            if ((unsigned)iy < 112u && (unsigned)ix < 112u)
                v = imgb[c * L_TOT + iy * 112 + ix];
            float w = wts[o * K_TOT + k];
            c1 += v * w; c2 += v * v * w; c3 += v * v * v * w;
        }
        out[(size_t)(b * C_OUT + o) * L_TOT + gm] = epilogue(g_wsum[o], c1, c2, c3);
    }
#endif
}

extern "C" void kernel_launch(void* const* d_in, const int* in_sizes, int n_in,
                              void* d_out, int out_size) {
    const float* img = (const float*)d_in[0];
    const float* wts = (const float*)d_in[1];
    float* out = (float*)d_out;

    int B = in_sizes[0] / (C_IN * L_TOT);   // 8

    cudaFuncSetAttribute(conv_tc_kernel, cudaFuncAttributeMaxDynamicSharedMemorySize, SMEM_TOTAL);
    rowsum_kernel<<<1, 64>>>(wts);
    conv_tc_kernel<<<B * 98, NTHREADS, SMEM_TOTAL>>>(img, wts, out);
}